// round 16
// baseline (speedup 1.0000x reference)
#include <cuda_runtime.h>
#include <cuda_fp16.h>
#include <stdint.h>

#define N_NODES 50000
#define N_EDGES 800000
#define IN_F    128
#define OUT_F   64

#define SA_STRIDE 136   // halves per smem row (128 + 8 pad -> conflict-free frags)
#define SH_STRIDE 72    // halves per epilogue staging row (64 + 8 pad)

#define CNT_PAD 53248   // 1024 threads * 52 ints, zero-padded

// Scratch (allocation-free rule: __device__ globals)
__device__ __half g_h[(size_t)N_NODES * OUT_F];     // 6.4 MB fp16 h table
__device__ __align__(16) int g_cnt[CNT_PAD];        // per-dst in-degree (zero at entry)
__device__ int  g_off[N_NODES + 1];                 // CSR offsets
__device__ int  g_cursor[N_NODES];                  // fill cursors
__device__ int2 g_srcw[N_EDGES];                    // CSR payload: (src, w-bits)

// ---------------------------------------------------------------------------
// GEMM: h = feat @ W^T + b  via mma.sync m16n8k16 (fp16 in, fp32 accum).
// Side-job: dst histogram (fire-and-forget, hidden under compute).
// No out-zeroing: the CSR gather writes every output row.
// ---------------------------------------------------------------------------
__global__ __launch_bounds__(256) void gemm_kernel(
    const float* __restrict__ feat,
    const float* __restrict__ W,
    const float* __restrict__ b,
    const int* __restrict__ edst)
{
    __shared__ __align__(16) __half sA[64 * SA_STRIDE];
    __shared__ __align__(16) __half sB[64 * SA_STRIDE];
    __shared__ float sBias[OUT_F];

    const int tid = threadIdx.x;
    const int node0 = blockIdx.x * 64;

    // Histogram side-job: 1024 edges per block (782 * 1024 >= 800000)
    {
        const int ebase = blockIdx.x * 1024 + tid;
        #pragma unroll
        for (int i = 0; i < 4; i++) {
            int e = ebase + i * 256;
            if (e < N_EDGES) atomicAdd(&g_cnt[edst[e]], 1);
        }
    }

    if (tid < OUT_F) sBias[tid] = b[tid];

    // Load W [64 x 128] fp32 -> fp16 smem
    {
        const float4* src = (const float4*)W;
        #pragma unroll
        for (int i = 0; i < 8; i++) {
            int idx = tid + i * 256;
            int o = idx >> 5, c4 = idx & 31;
            float4 v = src[idx];
            __half2 h01 = __floats2half2_rn(v.x, v.y);
            __half2 h23 = __floats2half2_rn(v.z, v.w);
            uint2 pk;
            pk.x = *(const unsigned int*)&h01;
            pk.y = *(const unsigned int*)&h23;
            *(uint2*)&sB[o * SA_STRIDE + c4 * 4] = pk;
        }
    }
    // Load 64 feat rows fp32 -> fp16 smem, zero-pad past N_NODES
    {
        const float4* src = (const float4*)feat;
        #pragma unroll
        for (int i = 0; i < 8; i++) {
            int idx = tid + i * 256;
            int n = idx >> 5, c4 = idx & 31;
            int node = node0 + n;
            float4 v = (node < N_NODES) ? src[(size_t)node * 32 + c4]
                                        : make_float4(0.f, 0.f, 0.f, 0.f);
            __half2 h01 = __floats2half2_rn(v.x, v.y);
            __half2 h23 = __floats2half2_rn(v.z, v.w);
            uint2 pk;
            pk.x = *(const unsigned int*)&h01;
            pk.y = *(const unsigned int*)&h23;
            *(uint2*)&sA[n * SA_STRIDE + c4 * 4] = pk;
        }
    }
    __syncthreads();

    const int lane = tid & 31;
    const int w    = tid >> 5;
    const int g    = lane >> 2;
    const int t    = lane & 3;
    const int mrow = (w >> 1) * 16;
    const int nbase = (w & 1) * 32;

    float c[4][4] = {};

    #pragma unroll
    for (int ks = 0; ks < 8; ks++) {
        const int k0 = ks * 16;
        const uint32_t a0 = *(const uint32_t*)&sA[(mrow + g    ) * SA_STRIDE + k0 + 2 * t];
        const uint32_t a1 = *(const uint32_t*)&sA[(mrow + g + 8) * SA_STRIDE + k0 + 2 * t];
        const uint32_t a2 = *(const uint32_t*)&sA[(mrow + g    ) * SA_STRIDE + k0 + 2 * t + 8];
        const uint32_t a3 = *(const uint32_t*)&sA[(mrow + g + 8) * SA_STRIDE + k0 + 2 * t + 8];
        #pragma unroll
        for (int nc = 0; nc < 4; nc++) {
            const int n = nbase + nc * 8 + g;
            const uint32_t b0 = *(const uint32_t*)&sB[n * SA_STRIDE + k0 + 2 * t];
            const uint32_t b1 = *(const uint32_t*)&sB[n * SA_STRIDE + k0 + 2 * t + 8];
            asm volatile(
                "mma.sync.aligned.m16n8k16.row.col.f32.f16.f16.f32 "
                "{%0,%1,%2,%3}, {%4,%5,%6,%7}, {%8,%9}, {%0,%1,%2,%3};"
                : "+f"(c[nc][0]), "+f"(c[nc][1]), "+f"(c[nc][2]), "+f"(c[nc][3])
                : "r"(a0), "r"(a1), "r"(a2), "r"(a3), "r"(b0), "r"(b1));
        }
    }

    // Epilogue: stage to smem (conflict-free), then coalesced uint4 STG
    __syncthreads();
    __half* sH = sA;
    #pragma unroll
    for (int nc = 0; nc < 4; nc++) {
        const int col = nbase + nc * 8 + 2 * t;
        const float b0f = sBias[col], b1f = sBias[col + 1];
        const __half2 h0 = __floats2half2_rn(c[nc][0] + b0f, c[nc][1] + b1f);
        const __half2 h1 = __floats2half2_rn(c[nc][2] + b0f, c[nc][3] + b1f);
        *(__half2*)&sH[(mrow + g    ) * SH_STRIDE + col] = h0;
        *(__half2*)&sH[(mrow + g + 8) * SH_STRIDE + col] = h1;
    }
    __syncthreads();
    #pragma unroll
    for (int i = 0; i < 2; i++) {
        int idx = tid + i * 256;
        int row = idx >> 3;
        int c16 = idx & 7;
        int node = node0 + row;
        if (node < N_NODES) {
            uint4 v = *(const uint4*)&sH[row * SH_STRIDE + c16 * 8];
            *(uint4*)(g_h + (size_t)node * OUT_F + c16 * 8) = v;
        }
    }
}

// ---------------------------------------------------------------------------
// Scan: exclusive prefix over g_cnt -> g_off + g_cursor, and RE-ZERO g_cnt
// (restores "g_cnt == 0 at entry" for graph replays). One block, 1024 threads.
// ---------------------------------------------------------------------------
__global__ __launch_bounds__(1024) void scan_kernel() {
    const int tid = threadIdx.x;
    int4* cnt4 = (int4*)g_cnt;

    int4 v[13];
    int sum = 0;
    #pragma unroll
    for (int c = 0; c < 13; c++) {
        v[c] = cnt4[tid * 13 + c];
        cnt4[tid * 13 + c] = make_int4(0, 0, 0, 0);   // re-zero for next call
        sum += v[c].x + v[c].y + v[c].z + v[c].w;
    }

    __shared__ int sbuf[2][1024];
    int cur = 0;
    sbuf[0][tid] = sum;
    __syncthreads();
    #pragma unroll
    for (int d = 1; d < 1024; d <<= 1) {
        int val = sbuf[cur][tid];
        if (tid >= d) val += sbuf[cur][tid - d];
        sbuf[cur ^ 1][tid] = val;
        cur ^= 1;
        __syncthreads();
    }
    int running = (tid == 0) ? 0 : sbuf[cur][tid - 1];   // exclusive

    const int base = tid * 52;
    #pragma unroll
    for (int c = 0; c < 13; c++) {
        int vals[4] = {v[c].x, v[c].y, v[c].z, v[c].w};
        #pragma unroll
        for (int q = 0; q < 4; q++) {
            int idx = base + c * 4 + q;
            if (idx < N_NODES) {
                g_off[idx] = running;
                g_cursor[idx] = running;
            } else if (idx == N_NODES) {
                g_off[N_NODES] = running;   // == N_EDGES
            }
            running += vals[q];
        }
    }
}

// ---------------------------------------------------------------------------
// Fill: place each edge's (src, weight) into its CSR slot. 4 edges/thread
// (MLP=4): batched coalesced loads, then independent atomic+store chains.
// ---------------------------------------------------------------------------
__global__ __launch_bounds__(256) void fill_kernel(
    const int* __restrict__ esrc,
    const int* __restrict__ edst,
    const float* __restrict__ ew)
{
    const int ebase = blockIdx.x * 1024 + threadIdx.x;

    int   s[4], d[4];
    float w[4];
    bool  ok[4];
    #pragma unroll
    for (int i = 0; i < 4; i++) {
        const int e = ebase + i * 256;
        ok[i] = (e < N_EDGES);
        s[i] = ok[i] ? esrc[e] : 0;
        d[i] = ok[i] ? edst[e] : 0;
        w[i] = ok[i] ? ew[e]   : 0.f;
    }
    #pragma unroll
    for (int i = 0; i < 4; i++) {
        if (ok[i]) {
            const int pos = atomicAdd(&g_cursor[d[i]], 1);
            g_srcw[pos] = make_int2(s[i], __float_as_int(w[i]));
        }
    }
}

// ---------------------------------------------------------------------------
// Gather-reduce: out[n] = sum_{e in CSR[n]} h[src_e] * w_e.  ZERO atomics;
// out RMW payload eliminated (plain coalesced stores, every row written).
// HALF-WARP per node: lane16 owns 4 floats; meta broadcast via 16-wide shfl.
// ---------------------------------------------------------------------------
__global__ __launch_bounds__(256) void gather_kernel(float* __restrict__ out) {
    const int tid  = threadIdx.x;
    const int hw   = tid >> 4;               // half-warp id in block, 0..15
    const int lane16 = tid & 15;
    const unsigned hmask = 0xFFFFu << (tid & 16);  // my half-warp's lane mask

    const int node = blockIdx.x * 16 + hw;   // 3125 * 16 = 50000 exactly
    const int start = g_off[node];
    const int end   = g_off[node + 1];

    float4 acc = make_float4(0.f, 0.f, 0.f, 0.f);

    for (int base = start; base < end; base += 16) {
        int2 meta = make_int2(0, 0);          // w = 0.0f -> safe zero term
        if (base + lane16 < end) meta = g_srcw[base + lane16];
        const int cnt = min(16, end - base);
        for (int j = 0; j < cnt; j++) {
            const int   s = __shfl_sync(hmask, meta.x, j, 16);
            const float w = __int_as_float(__shfl_sync(hmask, meta.y, j, 16));
            const uint2 hraw = *(const uint2*)(g_h + ((size_t)s << 6) + lane16 * 4);
            const float2 f0 = __half22float2(*(const __half2*)&hraw.x);
            const float2 f1 = __half22float2(*(const __half2*)&hraw.y);
            acc.x = fmaf(f0.x, w, acc.x);
            acc.y = fmaf(f0.y, w, acc.y);
            acc.z = fmaf(f1.x, w, acc.z);
            acc.w = fmaf(f1.y, w, acc.w);
        }
    }

    *(float4*)(out + ((size_t)node << 6) + lane16 * 4) = acc;  // 256 B/half-warp
}

// ---------------------------------------------------------------------------
extern "C" void kernel_launch(void* const* d_in, const int* in_sizes, int n_in,
                              void* d_out, int out_size) {
    const float* feat = (const float*)d_in[0];
    const int*   esrc = (const int*)d_in[1];   // int32 (JAX x64 disabled)
    const int*   edst = (const int*)d_in[2];
    const float* ew   = (const float*)d_in[3];
    const float* W    = (const float*)d_in[4];
    const float* b    = (const float*)d_in[5];
    float* out = (float*)d_out;

    gemm_kernel<<<(N_NODES + 63) / 64, 256>>>(feat, W, b, edst);   // + histogram

    scan_kernel<<<1, 1024>>>();

    fill_kernel<<<(N_EDGES + 1023) / 1024, 256>>>(esrc, edst, ew); // 782 blocks

    gather_kernel<<<N_NODES / 16, 256>>>(out);                     // 3125 blocks
}

// round 17
// speedup vs baseline: 2.3696x; 2.3696x over previous
#include <cuda_runtime.h>
#include <cuda_fp16.h>
#include <stdint.h>

#define N_NODES 50000
#define N_EDGES 800000
#define IN_F    128
#define OUT_F   64

#define SA_STRIDE 136   // halves per smem row (128 + 8 pad -> conflict-free frags)
#define SH_STRIDE 72    // halves per epilogue staging row (64 + 8 pad)

#define SC_THREADS 128  // scatter block: 4 warps, 32 edges, 8 KB smem
#define SC_EDGES   32

// Scratch (allocation-free rule: __device__ globals)
__device__ __half g_h[(size_t)N_NODES * OUT_F];  // 6.4 MB fp16 h table (L2-resident)

// ---------------------------------------------------------------------------
// GEMM: h = feat @ W^T + b  via mma.sync m16n8k16 (fp16 in, fp32 accum).
// 64x64 block tile, smem-staged coalesced epilogue. Side-job: zero `out`.
// ---------------------------------------------------------------------------
__global__ __launch_bounds__(256) void gemm_kernel(
    const float* __restrict__ feat,
    const float* __restrict__ W,
    const float* __restrict__ b,
    float4* __restrict__ out4)
{
    __shared__ __align__(16) __half sA[64 * SA_STRIDE];
    __shared__ __align__(16) __half sB[64 * SA_STRIDE];
    __shared__ float sBias[OUT_F];

    const int tid = threadIdx.x;
    const int node0 = blockIdx.x * 64;

    // Zero the output (independent side-job, hidden behind compute)
    {
        const int per_blk = (N_NODES * OUT_F / 4 + gridDim.x - 1) / gridDim.x;
        int base = blockIdx.x * per_blk;
        for (int i = tid; i < per_blk; i += 256) {
            int idx = base + i;
            if (idx < N_NODES * OUT_F / 4)
                out4[idx] = make_float4(0.f, 0.f, 0.f, 0.f);
        }
    }

    if (tid < OUT_F) sBias[tid] = b[tid];

    // Load W [64 x 128] fp32 -> fp16 smem (col-major B operand, no transpose)
    {
        const float4* src = (const float4*)W;
        #pragma unroll
        for (int i = 0; i < 8; i++) {
            int idx = tid + i * 256;
            int o = idx >> 5, c4 = idx & 31;
            float4 v = src[idx];
            __half2 h01 = __floats2half2_rn(v.x, v.y);
            __half2 h23 = __floats2half2_rn(v.z, v.w);
            uint2 pk;
            pk.x = *(const unsigned int*)&h01;
            pk.y = *(const unsigned int*)&h23;
            *(uint2*)&sB[o * SA_STRIDE + c4 * 4] = pk;
        }
    }
    // Load 64 feat rows fp32 -> fp16 smem, zero-pad past N_NODES
    {
        const float4* src = (const float4*)feat;
        #pragma unroll
        for (int i = 0; i < 8; i++) {
            int idx = tid + i * 256;
            int n = idx >> 5, c4 = idx & 31;
            int node = node0 + n;
            float4 v = (node < N_NODES) ? src[(size_t)node * 32 + c4]
                                        : make_float4(0.f, 0.f, 0.f, 0.f);
            __half2 h01 = __floats2half2_rn(v.x, v.y);
            __half2 h23 = __floats2half2_rn(v.z, v.w);
            uint2 pk;
            pk.x = *(const unsigned int*)&h01;
            pk.y = *(const unsigned int*)&h23;
            *(uint2*)&sA[n * SA_STRIDE + c4 * 4] = pk;
        }
    }
    __syncthreads();

    const int lane = tid & 31;
    const int w    = tid >> 5;
    const int g    = lane >> 2;        // groupID (row within 8)
    const int t    = lane & 3;         // thread-in-group (col pair)
    const int mrow = (w >> 1) * 16;    // local node base
    const int nbase = (w & 1) * 32;    // out-column base

    float c[4][4] = {};

    #pragma unroll
    for (int ks = 0; ks < 8; ks++) {
        const int k0 = ks * 16;
        const uint32_t a0 = *(const uint32_t*)&sA[(mrow + g    ) * SA_STRIDE + k0 + 2 * t];
        const uint32_t a1 = *(const uint32_t*)&sA[(mrow + g + 8) * SA_STRIDE + k0 + 2 * t];
        const uint32_t a2 = *(const uint32_t*)&sA[(mrow + g    ) * SA_STRIDE + k0 + 2 * t + 8];
        const uint32_t a3 = *(const uint32_t*)&sA[(mrow + g + 8) * SA_STRIDE + k0 + 2 * t + 8];
        #pragma unroll
        for (int nc = 0; nc < 4; nc++) {
            const int n = nbase + nc * 8 + g;
            const uint32_t b0 = *(const uint32_t*)&sB[n * SA_STRIDE + k0 + 2 * t];
            const uint32_t b1 = *(const uint32_t*)&sB[n * SA_STRIDE + k0 + 2 * t + 8];
            asm volatile(
                "mma.sync.aligned.m16n8k16.row.col.f32.f16.f16.f32 "
                "{%0,%1,%2,%3}, {%4,%5,%6,%7}, {%8,%9}, {%0,%1,%2,%3};"
                : "+f"(c[nc][0]), "+f"(c[nc][1]), "+f"(c[nc][2]), "+f"(c[nc][3])
                : "r"(a0), "r"(a1), "r"(a2), "r"(a3), "r"(b0), "r"(b1));
        }
    }

    // Epilogue: stage to smem (conflict-free), then coalesced uint4 STG
    __syncthreads();
    __half* sH = sA;
    #pragma unroll
    for (int nc = 0; nc < 4; nc++) {
        const int col = nbase + nc * 8 + 2 * t;
        const float b0f = sBias[col], b1f = sBias[col + 1];
        const __half2 h0 = __floats2half2_rn(c[nc][0] + b0f, c[nc][1] + b1f);
        const __half2 h1 = __floats2half2_rn(c[nc][2] + b0f, c[nc][3] + b1f);
        *(__half2*)&sH[(mrow + g    ) * SH_STRIDE + col] = h0;
        *(__half2*)&sH[(mrow + g + 8) * SH_STRIDE + col] = h1;
    }
    __syncthreads();
    #pragma unroll
    for (int i = 0; i < 2; i++) {
        int idx = tid + i * 256;
        int row = idx >> 3;
        int c16 = idx & 7;
        int node = node0 + row;
        if (node < N_NODES) {
            uint4 v = *(const uint4*)&sH[row * SH_STRIDE + c16 * 8];
            *(uint4*)(g_h + (size_t)node * OUT_F + c16 * 8) = v;
        }
    }
}

// ---------------------------------------------------------------------------
// Scatter: warp-autonomous cp.reduce.async.bulk, 128-thread blocks.
// Warp owns 8 edge rows: each half-warp gathers 4 rows (fp16, 8 B/lane),
// one __syncwarp, then lanes 0..7 each fence+issue one 256 B bulk atomic-add
// (fp32 accumulation at the L2), commit once, wait once. 32 edges/block,
// 8 KB smem -> 16 blocks/SM. Pinned at the L2 RMW-traffic roofline.
// ---------------------------------------------------------------------------
__global__ __launch_bounds__(SC_THREADS) void scatter_kernel(
    const int* __restrict__ esrc,
    const int* __restrict__ edst,
    const float* __restrict__ ew,
    float* __restrict__ out)
{
    __shared__ __align__(16) float sm[SC_EDGES * OUT_F];   // 8 KB: 32 edge rows

    const int tid  = threadIdx.x;
    const int warp = tid >> 5;            // 0..3, owns rows [warp*8, warp*8+8)
    const int lane = tid & 31;
    const int half = (tid >> 4) & 1;      // half-warp within warp
    const int lane16 = tid & 15;
    const int e0 = blockIdx.x * SC_EDGES; // N_EDGES % 32 == 0, no tail

    // Gather + scale: half-warp handles rows warp*8 + p*2 + half (4 rows, MLP=4)
    #pragma unroll
    for (int p = 0; p < 4; p++) {
        const int r = warp * 8 + p * 2 + half;
        const int e = e0 + r;
        const int   s = esrc[e];              // broadcast within half-warp
        const float w = ew[e];

        const uint2 hraw = *(const uint2*)(g_h + (size_t)s * OUT_F + lane16 * 4);
        const float2 f0 = __half22float2(*(const __half2*)&hraw.x);
        const float2 f1 = __half22float2(*(const __half2*)&hraw.y);
        float4 hv = make_float4(f0.x * w, f0.y * w, f1.x * w, f1.y * w);
        *(float4*)&sm[r * OUT_F + lane16 * 4] = hv;
    }
    __syncwarp();    // my warp's 8 rows staged (happens-before for the fence)

    // Lanes 0..7: one bulk atomic-add each for rows warp*8 + lane.
    if (lane < 8) {
        asm volatile("fence.proxy.async.shared::cta;" ::: "memory");
        const int r = warp * 8 + lane;
        const int d = edst[e0 + r];
        float* dst = out + (size_t)d * OUT_F;          // 256 B aligned
        uint32_t src_smem;
        asm("{ .reg .u64 t; cvta.to.shared.u64 t, %1; cvt.u32.u64 %0, t; }"
            : "=r"(src_smem) : "l"(&sm[r * OUT_F]));
        asm volatile(
            "cp.reduce.async.bulk.global.shared::cta.bulk_group.add.f32 "
            "[%0], [%1], %2;"
            :: "l"(dst), "r"(src_smem), "n"(OUT_F * 4)
            : "memory");
        asm volatile("cp.async.bulk.commit_group;" ::: "memory");
        asm volatile("cp.async.bulk.wait_group 0;" ::: "memory");
    }
}

// ---------------------------------------------------------------------------
extern "C" void kernel_launch(void* const* d_in, const int* in_sizes, int n_in,
                              void* d_out, int out_size) {
    const float* feat = (const float*)d_in[0];
    const int*   esrc = (const int*)d_in[1];   // int32 (JAX x64 disabled)
    const int*   edst = (const int*)d_in[2];
    const float* ew   = (const float*)d_in[3];
    const float* W    = (const float*)d_in[4];
    const float* b    = (const float*)d_in[5];
    float* out = (float*)d_out;

    gemm_kernel<<<(N_NODES + 63) / 64, 256>>>(feat, W, b, (float4*)out);

    scatter_kernel<<<N_EDGES / SC_EDGES, SC_THREADS>>>(esrc, edst, ew, out);  // 25000 blocks
}